// round 1
// baseline (speedup 1.0000x reference)
#include <cuda_runtime.h>

#define BATCH 4
#define CIN   256
#define CH    128
#define NN    4096   /* H*W = 64*64 */

// ---------------- scratch (device globals; no allocs allowed) ----------------
__device__ float g_T[BATCH][CH * NN];            // theta out, (ch,n) flat = x1 as (N,CH)
__device__ float g_F[BATCH][CH * NN];            // fi out, (ch,n)
__device__ float g_G[BATCH][CH * NN];            // gi out, flat = x3 as (N,CH)
__device__ float g_E[BATCH][NN * NN];            // exp(S)  (268 MB)
__device__ float g_Z[BATCH][NN];                 // column sums -> reciprocals
__device__ float g_Y[BATCH][NN * CH];            // y = attn @ x3, (N,CH) row-major

// ---------------- shared micro-kernel: 16-deep K step, 8x8 per thread --------
template <int LDB>
__device__ __forceinline__ void mma16(const float (*As)[128], const float (*Bs)[LDB],
                                      float (&acc)[8][8], int ty, int tx) {
#pragma unroll
    for (int kk = 0; kk < 16; kk++) {
        float a[8], b[8];
#pragma unroll
        for (int i = 0; i < 8; i++) a[i] = As[kk][ty * 8 + i];
#pragma unroll
        for (int j = 0; j < 8; j++) b[j] = Bs[kk][tx * 8 + j];
#pragma unroll
        for (int i = 0; i < 8; i++)
#pragma unroll
            for (int j = 0; j < 8; j++) acc[i][j] = fmaf(a[i], b[j], acc[i][j]);
    }
}

// ---------------- K0: zero the column-sum accumulators -----------------------
__global__ void __launch_bounds__(256) k_zero() {
    int i = blockIdx.x * 256 + threadIdx.x;          // 64 blocks * 256 = 16384
    (&g_Z[0][0])[i] = 0.0f;
}

// ---------------- K1: theta/fi/gi 1x1 convs (GEMM 128x4096x256 per section) --
__global__ void __launch_bounds__(256) k_qkv(
    const float* __restrict__ x,
    const float* __restrict__ tw, const float* __restrict__ tb,
    const float* __restrict__ fw, const float* __restrict__ fb,
    const float* __restrict__ gw, const float* __restrict__ gb)
{
    const int b   = blockIdx.z;
    const int sec = blockIdx.y;            // 0: theta, 1: fi, 2: gi
    const int n0  = blockIdx.x * 128;
    const float* W   = sec == 0 ? tw : (sec == 1 ? fw : gw);
    const float* Bv  = sec == 0 ? tb : (sec == 1 ? fb : gb);
    float*       Dst = sec == 0 ? g_T[b] : (sec == 1 ? g_F[b] : g_G[b]);
    const float* X   = x + (size_t)b * CIN * NN;

    __shared__ float As[16][128];
    __shared__ float Bs[16][128];
    const int tid = threadIdx.x, tx = tid & 15, ty = tid >> 4;
    float acc[8][8] = {};

    for (int k0 = 0; k0 < CIN; k0 += 16) {
#pragma unroll
        for (int l = 0; l < 8; l++) {                 // A tile: 128 rows x 16 k
            int idx = tid + l * 256;
            int r = idx >> 4, kk = idx & 15;
            As[kk][r] = W[r * CIN + k0 + kk];
        }
#pragma unroll
        for (int l = 0; l < 8; l++) {                 // B tile: 16 k x 128 cols
            int idx = tid + l * 256;
            int kk = idx >> 7, nn = idx & 127;
            Bs[kk][nn] = X[(k0 + kk) * NN + n0 + nn];
        }
        __syncthreads();
        mma16<128>(As, Bs, acc, ty, tx);
        __syncthreads();
    }
#pragma unroll
    for (int i = 0; i < 8; i++) {
        int r = ty * 8 + i;
        float bias = Bv[r];
        float* d = Dst + r * NN + n0 + tx * 8;
        float4 v0 = make_float4(acc[i][0] + bias, acc[i][1] + bias, acc[i][2] + bias, acc[i][3] + bias);
        float4 v1 = make_float4(acc[i][4] + bias, acc[i][5] + bias, acc[i][6] + bias, acc[i][7] + bias);
        *(float4*)(d)     = v0;
        *(float4*)(d + 4) = v1;
    }
}

// ---------------- K2: E = exp(x1 @ x2), fused column-sum accumulation --------
__global__ void __launch_bounds__(256) k_scores() {
    const int b  = blockIdx.z;
    const int i0 = blockIdx.y * 128;
    const int j0 = blockIdx.x * 128;
    const float* A  = g_T[b];   // (N x CH) row-major (flat reinterpretation)
    const float* Bm = g_F[b];   // (CH x N) row-major
    float*       E  = g_E[b];

    __shared__ float As[16][128];
    __shared__ float Bs[16][128];
    const int tid = threadIdx.x, tx = tid & 15, ty = tid >> 4;
    float acc[8][8] = {};

    for (int k0 = 0; k0 < CH; k0 += 16) {
#pragma unroll
        for (int l = 0; l < 8; l++) {
            int idx = tid + l * 256;
            int r = idx >> 4, kk = idx & 15;
            As[kk][r] = A[(i0 + r) * CH + k0 + kk];
        }
#pragma unroll
        for (int l = 0; l < 8; l++) {
            int idx = tid + l * 256;
            int kk = idx >> 7, nn = idx & 127;
            Bs[kk][nn] = Bm[(k0 + kk) * NN + j0 + nn];
        }
        __syncthreads();
        mma16<128>(As, Bs, acc, ty, tx);
        __syncthreads();
    }

    // epilogue: exp, store, per-thread column partials
    float colsum[8] = {};
#pragma unroll
    for (int i = 0; i < 8; i++) {
        float e[8];
#pragma unroll
        for (int j = 0; j < 8; j++) { e[j] = __expf(acc[i][j]); colsum[j] += e[j]; }
        float* d = E + (size_t)(i0 + ty * 8 + i) * NN + j0 + tx * 8;
        *(float4*)(d)     = make_float4(e[0], e[1], e[2], e[3]);
        *(float4*)(d + 4) = make_float4(e[4], e[5], e[6], e[7]);
    }
    // reduce partials over the 16 ty-groups (reuse As), one atomic per column
    __syncthreads();
#pragma unroll
    for (int j = 0; j < 8; j++) As[ty][tx * 8 + j] = colsum[j];
    __syncthreads();
    if (tid < 128) {
        float s = 0.f;
#pragma unroll
        for (int t = 0; t < 16; t++) s += As[t][tid];
        atomicAdd(&g_Z[b][j0 + tid], s);
    }
}

// ---------------- K3: Z -> 1/Z ----------------------------------------------
__global__ void __launch_bounds__(256) k_recip() {
    int i = blockIdx.x * 256 + threadIdx.x;
    float* z = &g_Z[0][0];
    z[i] = 1.0f / z[i];
}

// ---------------- K4: Y = (E * invZ_col) @ x3  (M=4096, N=128, K=4096) -------
__global__ void __launch_bounds__(256) k_attnv() {
    const int b  = blockIdx.y;
    const int i0 = blockIdx.x * 128;
    const float* E  = g_E[b];
    const float* G  = g_G[b];       // (N x CH) row-major flat
    const float* rZ = g_Z[b];       // holds 1/Z after k_recip
    float*       Y  = g_Y[b];

    __shared__ float As[16][128];
    __shared__ float Bs[16][128];
    const int tid = threadIdx.x, tx = tid & 15, ty = tid >> 4;
    float acc[8][8] = {};

    for (int k0 = 0; k0 < NN; k0 += 16) {
#pragma unroll
        for (int l = 0; l < 8; l++) {                 // A: E rows, scaled by invZ[col j]
            int idx = tid + l * 256;
            int r = idx >> 4, kk = idx & 15;
            As[kk][r] = E[(size_t)(i0 + r) * NN + k0 + kk] * rZ[k0 + kk];
        }
#pragma unroll
        for (int l = 0; l < 8; l++) {                 // B: G rows (K-dim) x CH cols
            int idx = tid + l * 256;
            int kk = idx >> 7, nn = idx & 127;
            Bs[kk][nn] = G[(k0 + kk) * CH + nn];
        }
        __syncthreads();
        mma16<128>(As, Bs, acc, ty, tx);
        __syncthreads();
    }
#pragma unroll
    for (int i = 0; i < 8; i++) {
        float* d = Y + (i0 + ty * 8 + i) * CH + tx * 8;
        *(float4*)(d)     = make_float4(acc[i][0], acc[i][1], acc[i][2], acc[i][3]);
        *(float4*)(d + 4) = make_float4(acc[i][4], acc[i][5], acc[i][6], acc[i][7]);
    }
}

// ---------------- K5: out = x + out_w @ Y^T + out_b --------------------------
__global__ void __launch_bounds__(256) k_out(
    const float* __restrict__ x,
    const float* __restrict__ ow, const float* __restrict__ ob,
    float* __restrict__ out)
{
    const int b  = blockIdx.z;
    const int m0 = blockIdx.y * 128;     // output channel tile (C=256 -> 2)
    const int n0 = blockIdx.x * 128;     // spatial tile
    const float* Y = g_Y[b];

    __shared__ float As[16][128];
    __shared__ float Bs[16][132];        // padded: transposed Y loads
    const int tid = threadIdx.x, tx = tid & 15, ty = tid >> 4;
    float acc[8][8] = {};

    for (int k0 = 0; k0 < CH; k0 += 16) {
#pragma unroll
        for (int l = 0; l < 8; l++) {
            int idx = tid + l * 256;
            int r = idx >> 4, kk = idx & 15;
            As[kk][r] = ow[(m0 + r) * CH + k0 + kk];
        }
#pragma unroll
        for (int l = 0; l < 8; l++) {                 // B[k][p] = Y[p*CH + k]
            int idx = tid + l * 256;
            int nn = idx >> 4, kk = idx & 15;
            Bs[kk][nn] = Y[(n0 + nn) * CH + k0 + kk];
        }
        __syncthreads();
        mma16<132>(As, Bs, acc, ty, tx);
        __syncthreads();
    }
#pragma unroll
    for (int i = 0; i < 8; i++) {
        int r = m0 + ty * 8 + i;
        float bias = ob[r];
        size_t base = ((size_t)b * CIN + r) * NN + n0 + tx * 8;
        float4 x0 = *(const float4*)(x + base);
        float4 x1 = *(const float4*)(x + base + 4);
        float4 o0 = make_float4(acc[i][0] + bias + x0.x, acc[i][1] + bias + x0.y,
                                acc[i][2] + bias + x0.z, acc[i][3] + bias + x0.w);
        float4 o1 = make_float4(acc[i][4] + bias + x1.x, acc[i][5] + bias + x1.y,
                                acc[i][6] + bias + x1.z, acc[i][7] + bias + x1.w);
        *(float4*)(out + base)     = o0;
        *(float4*)(out + base + 4) = o1;
    }
}

// -----------------------------------------------------------------------------
extern "C" void kernel_launch(void* const* d_in, const int* in_sizes, int n_in,
                              void* d_out, int out_size) {
    const float* x  = (const float*)d_in[0];
    const float* tw = (const float*)d_in[1];
    const float* tb = (const float*)d_in[2];
    const float* fw = (const float*)d_in[3];
    const float* fb = (const float*)d_in[4];
    const float* gw = (const float*)d_in[5];
    const float* gb = (const float*)d_in[6];
    const float* ow = (const float*)d_in[7];
    const float* ob = (const float*)d_in[8];
    float* out = (float*)d_out;

    k_zero<<<64, 256>>>();                               // zero g_Z (16384 elems)
    dim3 g1(32, 3, BATCH);
    k_qkv<<<g1, 256>>>(x, tw, tb, fw, fb, gw, gb);       // theta/fi/gi
    dim3 g2(32, 32, BATCH);
    k_scores<<<g2, 256>>>();                             // E = exp(S), col sums
    k_recip<<<64, 256>>>();                              // Z -> 1/Z
    dim3 g4(32, BATCH);
    k_attnv<<<g4, 256>>>();                              // Y = attn @ x3
    dim3 g5(32, 2, BATCH);
    k_out<<<g5, 256>>>(x, ow, ob, out);                  // residual + out conv
}

// round 3
// speedup vs baseline: 3.7599x; 3.7599x over previous
#include <cuda_runtime.h>
#include <cstdint>

#define BATCH 4
#define CIN   256
#define CH    128
#define NN    4096
#define ROWF  36          /* padded tile row length in floats (9 x 16B) */
#define KSPLIT 8

// ---------------- scratch (device globals; no allocs allowed) ----------------
__device__ float g_Xt[BATCH][NN * CIN];            // x transposed: (NN, CIN)
__device__ float g_T [BATCH][CH * NN];             // theta out (CH,NN) flat == x1 (N,CH)
__device__ float g_F [BATCH][CH * NN];             // fi out (CH,NN)
__device__ float g_G [BATCH][CH * NN];             // gi out flat == x3 (N,CH)
__device__ float g_Ft[BATCH][NN * CH];             // F^T: (NN, CH)
__device__ float g_Gt[BATCH][CH * NN];             // x3^T * invZ: (CH, NN)
__device__ float g_E [BATCH][(size_t)NN * NN];     // exp(S)
__device__ float g_Z [BATCH][NN];                  // column sums -> reciprocals
__device__ float g_Yp[KSPLIT][BATCH][NN * CH];     // split-K partials of Y

// ====================== helpers (baseline PTX only) ==========================
__device__ __forceinline__ uint32_t smem_u32(const void* p) {
    uint32_t a;
    asm("{ .reg .u64 t; cvta.to.shared.u64 t, %1; cvt.u32.u64 %0, t; }" : "=r"(a) : "l"(p));
    return a;
}
__device__ __forceinline__ float tf32_rna(float a) {
    uint32_t u; asm("cvt.rna.tf32.f32 %0, %1;" : "=r"(u) : "f"(a));
    return __uint_as_float(u);
}
__device__ __forceinline__ void ldsm4(uint32_t& r0, uint32_t& r1, uint32_t& r2, uint32_t& r3,
                                      uint32_t addr) {
    asm volatile("ldmatrix.sync.aligned.m8n8.x4.shared.b16 {%0,%1,%2,%3}, [%4];"
                 : "=r"(r0), "=r"(r1), "=r"(r2), "=r"(r3) : "r"(addr));
}
__device__ __forceinline__ void mma_tf32(float (&d)[4], const uint32_t (&a)[4],
                                         uint32_t b0, uint32_t b1) {
    asm volatile("mma.sync.aligned.m16n8k8.row.col.f32.tf32.tf32.f32 "
                 "{%0,%1,%2,%3}, {%4,%5,%6,%7}, {%8,%9}, {%0,%1,%2,%3};"
                 : "+f"(d[0]), "+f"(d[1]), "+f"(d[2]), "+f"(d[3])
                 : "r"(a[0]), "r"(a[1]), "r"(a[2]), "r"(a[3]), "r"(b0), "r"(b1));
}
// exp on the FMA pipe (no MUFU): exp(x) = 2^(x*log2e), deg-5 poly on [-.5,.5]
__device__ __forceinline__ float fast_exp(float x) {
    float y = x * 1.4426950408889634f;
    int ni = __float2int_rn(y);
    ni = max(ni, -120);
    float f = y - (float)ni;
    float p = 1.3333558146e-3f;
    p = fmaf(p, f, 9.6181291076e-3f);
    p = fmaf(p, f, 5.5504108665e-2f);
    p = fmaf(p, f, 2.4022650696e-1f);
    p = fmaf(p, f, 6.9314718056e-1f);
    p = fmaf(p, f, 1.0f);
    return __int_as_float(__float_as_int(p) + (ni << 23));
}

// stage a 128x32 float slice into [128][ROWF] smem as tf32 (conflict-free phases)
__device__ __forceinline__ void stage_tile(float* s, const float* src, size_t rstride,
                                           int row0, int k0, int tid) {
#pragma unroll
    for (int it = 0; it < 4; it++) {
        int idx = tid + it * 256;
        int m = idx >> 3, k4 = idx & 7;
        float4 v = *(const float4*)(src + (size_t)(row0 + m) * rstride + k0 + k4 * 4);
        v.x = tf32_rna(v.x); v.y = tf32_rna(v.y); v.z = tf32_rna(v.z); v.w = tf32_rna(v.w);
        *(float4*)(s + m * ROWF + k4 * 4) = v;
    }
}

// ---------------- tiny kernels ----------------------------------------------
__global__ void __launch_bounds__(256) k_zero() {
    int i = blockIdx.x * 256 + threadIdx.x;          // 64*256 = BATCH*NN
    (&g_Z[0][0])[i] = 0.0f;
}
__global__ void __launch_bounds__(256) k_recip() {
    int i = blockIdx.x * 256 + threadIdx.x;
    float* z = &g_Z[0][0];
    z[i] = 1.0f / z[i];
}

// ---------------- transposes -------------------------------------------------
__global__ void __launch_bounds__(256) k_transX(const float* __restrict__ x) {
    __shared__ float t[32][33];
    const int b = blockIdx.z;
    const float* src = x + (size_t)b * CIN * NN;
    float* dst = g_Xt[b];
    const int c0 = blockIdx.x * 32, r0 = blockIdx.y * 32;   // c over NN, r over CIN
    const int tx = threadIdx.x, ty = threadIdx.y;
#pragma unroll
    for (int j = 0; j < 32; j += 8) t[ty + j][tx] = src[(size_t)(r0 + ty + j) * NN + c0 + tx];
    __syncthreads();
#pragma unroll
    for (int j = 0; j < 32; j += 8) dst[(size_t)(c0 + ty + j) * CIN + r0 + tx] = t[tx][ty + j];
}
__global__ void __launch_bounds__(256) k_transF() {
    __shared__ float t[32][33];
    const int b = blockIdx.z;
    const float* src = g_F[b];
    float* dst = g_Ft[b];
    const int c0 = blockIdx.x * 32, r0 = blockIdx.y * 32;   // c over NN, r over CH
    const int tx = threadIdx.x, ty = threadIdx.y;
#pragma unroll
    for (int j = 0; j < 32; j += 8) t[ty + j][tx] = src[(size_t)(r0 + ty + j) * NN + c0 + tx];
    __syncthreads();
#pragma unroll
    for (int j = 0; j < 32; j += 8) dst[(size_t)(c0 + ty + j) * CH + r0 + tx] = t[tx][ty + j];
}
__global__ void __launch_bounds__(256) k_transG() {
    __shared__ float t[32][33];
    const int b = blockIdx.z;
    const float* src = g_G[b];          // flat == x3 (NN,CH)
    const float* rZ  = g_Z[b];
    float* dst = g_Gt[b];
    const int c0 = blockIdx.x * 32;     // over CH
    const int r0 = blockIdx.y * 32;     // over NN
    const int tx = threadIdx.x, ty = threadIdx.y;
#pragma unroll
    for (int j = 0; j < 32; j += 8)
        t[ty + j][tx] = src[(size_t)(r0 + ty + j) * CH + c0 + tx] * rZ[r0 + ty + j];
    __syncthreads();
#pragma unroll
    for (int j = 0; j < 32; j += 8) dst[(size_t)(c0 + ty + j) * NN + r0 + tx] = t[tx][ty + j];
}

// ---------------- K1: theta/fi/gi convs via tensor mma -----------------------
__global__ void __launch_bounds__(256, 2) k_qkv_mma(
    const float* __restrict__ tw, const float* __restrict__ tb,
    const float* __restrict__ fw, const float* __restrict__ fb,
    const float* __restrict__ gw, const float* __restrict__ gb)
{
    __shared__ float sA[128 * ROWF];
    __shared__ float sB[128 * ROWF];
    const int tid = threadIdx.x, lane = tid & 31, wid = tid >> 5;
    const int b = blockIdx.z, sec = blockIdx.y, j0 = blockIdx.x * 128;
    const float* W  = sec == 0 ? tw : (sec == 1 ? fw : gw);
    const float* Bv = sec == 0 ? tb : (sec == 1 ? fb : gb);
    float*      Dst = sec == 0 ? g_T[b] : (sec == 1 ? g_F[b] : g_G[b]);
    const float* Xt = g_Xt[b];

    const int g = lane >> 2, tg = lane & 3;
    const int quad = lane >> 3, lrow = lane & 7;
    const int M0 = (wid & 3) * 32, N0 = (wid >> 2) * 64;
    const uint32_t aB = smem_u32(sA) + ((M0 + (quad & 1) * 8 + lrow) * ROWF) * 4 + (quad >> 1) * 16;
    const uint32_t bB = smem_u32(sB) + ((N0 + (quad >> 1) * 8 + lrow) * ROWF) * 4 + (quad & 1) * 16;

    float acc[2][8][4] = {};
    for (int k0 = 0; k0 < CIN; k0 += 32) {
        stage_tile(sA, W, CIN, 0, k0, tid);
        stage_tile(sB, Xt, CIN, j0, k0, tid);
        __syncthreads();
#pragma unroll
        for (int k8 = 0; k8 < 4; k8++) {
            uint32_t af[2][4];
#pragma unroll
            for (int mt = 0; mt < 2; mt++)
                ldsm4(af[mt][0], af[mt][1], af[mt][2], af[mt][3],
                      aB + mt * (16 * ROWF * 4) + k8 * 32);
#pragma unroll
            for (int bp = 0; bp < 4; bp++) {
                uint32_t q0, q1, q2, q3;
                ldsm4(q0, q1, q2, q3, bB + bp * (16 * ROWF * 4) + k8 * 32);
#pragma unroll
                for (int mt = 0; mt < 2; mt++) {
                    mma_tf32(acc[mt][2 * bp],     af[mt], q0, q1);
                    mma_tf32(acc[mt][2 * bp + 1], af[mt], q2, q3);
                }
            }
        }
        __syncthreads();
    }
#pragma unroll
    for (int mt = 0; mt < 2; mt++) {
        int r = M0 + mt * 16 + g;
        float b0 = Bv[r], b1 = Bv[r + 8];
#pragma unroll
        for (int nt = 0; nt < 8; nt++) {
            int c = j0 + N0 + nt * 8 + 2 * tg;
            *(float2*)(Dst + (size_t)r * NN + c)       = make_float2(acc[mt][nt][0] + b0, acc[mt][nt][1] + b0);
            *(float2*)(Dst + (size_t)(r + 8) * NN + c) = make_float2(acc[mt][nt][2] + b1, acc[mt][nt][3] + b1);
        }
    }
}

// ---------------- K2: E = exp(x1 @ x2), tensor mma, fused col-sums -----------
__global__ void __launch_bounds__(256, 2) k_scores_mma() {
    __shared__ float sA[128 * ROWF];
    __shared__ float sB[128 * ROWF];
    const int tid = threadIdx.x, lane = tid & 31, wid = tid >> 5;
    const int b = blockIdx.z, i0 = blockIdx.y * 128, j0 = blockIdx.x * 128;
    const float* A  = g_T[b];            // (N, CH)
    const float* Bm = g_Ft[b];           // (N, CH)
    float*       E  = g_E[b];

    const int g = lane >> 2, tg = lane & 3;
    const int quad = lane >> 3, lrow = lane & 7;
    const int M0 = (wid & 3) * 32, N0 = (wid >> 2) * 64;
    const uint32_t aB = smem_u32(sA) + ((M0 + (quad & 1) * 8 + lrow) * ROWF) * 4 + (quad >> 1) * 16;
    const uint32_t bB = smem_u32(sB) + ((N0 + (quad >> 1) * 8 + lrow) * ROWF) * 4 + (quad & 1) * 16;

    float acc[2][8][4] = {};
    for (int k0 = 0; k0 < CH; k0 += 32) {
        stage_tile(sA, A, CH, i0, k0, tid);
        stage_tile(sB, Bm, CH, j0, k0, tid);
        __syncthreads();
#pragma unroll
        for (int k8 = 0; k8 < 4; k8++) {
            uint32_t af[2][4];
#pragma unroll
            for (int mt = 0; mt < 2; mt++)
                ldsm4(af[mt][0], af[mt][1], af[mt][2], af[mt][3],
                      aB + mt * (16 * ROWF * 4) + k8 * 32);
#pragma unroll
            for (int bp = 0; bp < 4; bp++) {
                uint32_t q0, q1, q2, q3;
                ldsm4(q0, q1, q2, q3, bB + bp * (16 * ROWF * 4) + k8 * 32);
#pragma unroll
                for (int mt = 0; mt < 2; mt++) {
                    mma_tf32(acc[mt][2 * bp],     af[mt], q0, q1);
                    mma_tf32(acc[mt][2 * bp + 1], af[mt], q2, q3);
                }
            }
        }
        __syncthreads();
    }
    // epilogue: exp (FMA-pipe), store E, fused column sums over i
#pragma unroll
    for (int nt = 0; nt < 8; nt++) {
        float cs0 = 0.f, cs1 = 0.f;
#pragma unroll
        for (int mt = 0; mt < 2; mt++) {
            float e0 = fast_exp(acc[mt][nt][0]);
            float e1 = fast_exp(acc[mt][nt][1]);
            float e2 = fast_exp(acc[mt][nt][2]);
            float e3 = fast_exp(acc[mt][nt][3]);
            int r = i0 + M0 + mt * 16 + g;
            int c = j0 + N0 + nt * 8 + 2 * tg;
            *(float2*)(E + (size_t)r * NN + c)       = make_float2(e0, e1);
            *(float2*)(E + (size_t)(r + 8) * NN + c) = make_float2(e2, e3);
            cs0 += e0 + e2;
            cs1 += e1 + e3;
        }
        cs0 += __shfl_xor_sync(0xFFFFFFFFu, cs0, 4);
        cs0 += __shfl_xor_sync(0xFFFFFFFFu, cs0, 8);
        cs0 += __shfl_xor_sync(0xFFFFFFFFu, cs0, 16);
        cs1 += __shfl_xor_sync(0xFFFFFFFFu, cs1, 4);
        cs1 += __shfl_xor_sync(0xFFFFFFFFu, cs1, 8);
        cs1 += __shfl_xor_sync(0xFFFFFFFFu, cs1, 16);
        if (lane < 4) {
            int c = j0 + N0 + nt * 8 + 2 * tg;
            atomicAdd(&g_Z[b][c],     cs0);
            atomicAdd(&g_Z[b][c + 1], cs1);
        }
    }
}

// ---------------- K4: Yp[ks] = E-slice @ (Gt*invZ)^T, tensor mma -------------
__global__ void __launch_bounds__(256, 2) k_attnv_mma() {
    __shared__ float sA[128 * ROWF];
    __shared__ float sB[128 * ROWF];
    const int tid = threadIdx.x, lane = tid & 31, wid = tid >> 5;
    const int ks = blockIdx.x, i0 = blockIdx.y * 128, b = blockIdx.z;
    const int kbase = ks * (NN / KSPLIT);
    const float* E  = g_E[b];
    const float* Gt = g_Gt[b];           // (CH, NN)
    float*       Yp = g_Yp[ks][b];

    const int g = lane >> 2, tg = lane & 3;
    const int quad = lane >> 3, lrow = lane & 7;
    const int M0 = (wid & 3) * 32, N0 = (wid >> 2) * 64;
    const uint32_t aB = smem_u32(sA) + ((M0 + (quad & 1) * 8 + lrow) * ROWF) * 4 + (quad >> 1) * 16;
    const uint32_t bB = smem_u32(sB) + ((N0 + (quad >> 1) * 8 + lrow) * ROWF) * 4 + (quad & 1) * 16;

    float acc[2][8][4] = {};
    for (int cc = 0; cc < (NN / KSPLIT) / 32; cc++) {
        const int k0 = kbase + cc * 32;
        stage_tile(sA, E, NN, i0, k0, tid);
        stage_tile(sB, Gt, NN, 0, k0, tid);
        __syncthreads();
#pragma unroll
        for (int k8 = 0; k8 < 4; k8++) {
            uint32_t af[2][4];
#pragma unroll
            for (int mt = 0; mt < 2; mt++)
                ldsm4(af[mt][0], af[mt][1], af[mt][2], af[mt][3],
                      aB + mt * (16 * ROWF * 4) + k8 * 32);
#pragma unroll
            for (int bp = 0; bp < 4; bp++) {
                uint32_t q0, q1, q2, q3;
                ldsm4(q0, q1, q2, q3, bB + bp * (16 * ROWF * 4) + k8 * 32);
#pragma unroll
                for (int mt = 0; mt < 2; mt++) {
                    mma_tf32(acc[mt][2 * bp],     af[mt], q0, q1);
                    mma_tf32(acc[mt][2 * bp + 1], af[mt], q2, q3);
                }
            }
        }
        __syncthreads();
    }
#pragma unroll
    for (int mt = 0; mt < 2; mt++) {
        int r = i0 + M0 + mt * 16 + g;
#pragma unroll
        for (int nt = 0; nt < 8; nt++) {
            int c = N0 + nt * 8 + 2 * tg;
            *(float2*)(Yp + (size_t)r * CH + c)       = make_float2(acc[mt][nt][0], acc[mt][nt][1]);
            *(float2*)(Yp + (size_t)(r + 8) * CH + c) = make_float2(acc[mt][nt][2], acc[mt][nt][3]);
        }
    }
}

// ---------------- K5: out = x + out_w @ Y^T + out_b (exact fp32) -------------
template <int LDB>
__device__ __forceinline__ void mma16f(const float (*As)[128], const float (*Bs)[LDB],
                                       float (&acc)[8][8], int ty, int tx) {
#pragma unroll
    for (int kk = 0; kk < 16; kk++) {
        float a[8], b[8];
#pragma unroll
        for (int i = 0; i < 8; i++) a[i] = As[kk][ty * 8 + i];
#pragma unroll
        for (int j = 0; j < 8; j++) b[j] = Bs[kk][tx * 8 + j];
#pragma unroll
        for (int i = 0; i < 8; i++)
#pragma unroll
            for (int j = 0; j < 8; j++) acc[i][j] = fmaf(a[i], b[j], acc[i][j]);
    }
}
__global__ void __launch_bounds__(256) k_out(
    const float* __restrict__ x,
    const float* __restrict__ ow, const float* __restrict__ ob,
    float* __restrict__ out)
{
    const int b  = blockIdx.z;
    const int m0 = blockIdx.y * 128;
    const int n0 = blockIdx.x * 128;

    __shared__ float As[16][128];
    __shared__ float Bs[16][132];
    const int tid = threadIdx.x, tx = tid & 15, ty = tid >> 4;
    float acc[8][8] = {};

    for (int k0 = 0; k0 < CH; k0 += 16) {
#pragma unroll
        for (int l = 0; l < 8; l++) {
            int idx = tid + l * 256;
            int r = idx >> 4, kk = idx & 15;
            As[kk][r] = ow[(m0 + r) * CH + k0 + kk];
        }
#pragma unroll
        for (int l = 0; l < 8; l++) {
            int idx = tid + l * 256;
            int nn = idx >> 4, kk = idx & 15;
            size_t src = (size_t)(n0 + nn) * CH + k0 + kk;
            float s = 0.f;
#pragma unroll
            for (int q = 0; q < KSPLIT; q++) s += g_Yp[q][b][src];
            Bs[kk][nn] = s;
        }
        __syncthreads();
        mma16f<132>(As, Bs, acc, ty, tx);
        __syncthreads();
    }
#pragma unroll
    for (int i = 0; i < 8; i++) {
        int r = m0 + ty * 8 + i;
        float bias = ob[r];
        size_t bofs = ((size_t)b * CIN + r) * NN + n0 + tx * 8;
        float4 x0 = *(const float4*)(x + bofs);
        float4 x1 = *(const float4*)(x + bofs + 4);
        *(float4*)(out + bofs)     = make_float4(acc[i][0] + bias + x0.x, acc[i][1] + bias + x0.y,
                                                 acc[i][2] + bias + x0.z, acc[i][3] + bias + x0.w);
        *(float4*)(out + bofs + 4) = make_float4(acc[i][4] + bias + x1.x, acc[i][5] + bias + x1.y,
                                                 acc[i][6] + bias + x1.z, acc[i][7] + bias + x1.w);
    }
}

// -----------------------------------------------------------------------------
extern "C" void kernel_launch(void* const* d_in, const int* in_sizes, int n_in,
                              void* d_out, int out_size) {
    const float* x  = (const float*)d_in[0];
    const float* tw = (const float*)d_in[1];
    const float* tb = (const float*)d_in[2];
    const float* fw = (const float*)d_in[3];
    const float* fb = (const float*)d_in[4];
    const float* gw = (const float*)d_in[5];
    const float* gb = (const float*)d_in[6];
    const float* ow = (const float*)d_in[7];
    const float* ob = (const float*)d_in[8];
    float* out = (float*)d_out;

    k_zero<<<64, 256>>>();
    k_transX<<<dim3(128, 8, BATCH), dim3(32, 8)>>>(x);
    k_qkv_mma<<<dim3(32, 3, BATCH), 256>>>(tw, tb, fw, fb, gw, gb);
    k_transF<<<dim3(128, 4, BATCH), dim3(32, 8)>>>();
    k_scores_mma<<<dim3(32, 32, BATCH), 256>>>();
    k_recip<<<64, 256>>>();
    k_transG<<<dim3(4, 128, BATCH), dim3(32, 8)>>>();
    k_attnv_mma<<<dim3(KSPLIT, 32, BATCH), 256>>>();
    k_out<<<dim3(32, 2, BATCH), 256>>>(x, ow, ob, out);
}

// round 4
// speedup vs baseline: 4.0959x; 1.0894x over previous
#include <cuda_runtime.h>
#include <cuda_fp16.h>
#include <cuda_bf16.h>
#include <cstdint>

#define BATCH 4
#define CIN   256
#define CH    128
#define NN    4096
#define ROWH  40          /* padded smem row length in 16-bit elems (80 B) */
#define KSPLIT 4

// ---------------- scratch (device globals; no allocs allowed) ----------------
__device__ __half          g_Xt[BATCH][NN * CIN];        // x^T: (NN, CIN) fp16
__device__ __half          g_T [BATCH][CH * NN];         // theta out (CH,NN) flat == x1 (N,CH)
__device__ __half          g_G [BATCH][CH * NN];         // gi out flat == x3 (N,CH)
__device__ __half          g_Ft[BATCH][NN * CH];         // fi out computed directly as (NN, CH)
__device__ __nv_bfloat16   g_Gt[BATCH][CH * NN];         // x3^T * invZ: (CH, NN) bf16
__device__ __nv_bfloat16   g_E [BATCH][(size_t)NN * NN]; // exp(S) bf16
__device__ float           g_Z [BATCH][NN];              // column sums -> reciprocals
__device__ float           g_Yp[KSPLIT][BATCH][NN * CH]; // split-K partials of Y (fp32)
__device__ __half          g_Y [BATCH][NN * CH];         // summed Y (N,CH) fp16

// ====================== helpers (baseline PTX only) ==========================
__device__ __forceinline__ uint32_t smem_u32(const void* p) {
    uint32_t a;
    asm("{ .reg .u64 t; cvta.to.shared.u64 t, %1; cvt.u32.u64 %0, t; }" : "=r"(a) : "l"(p));
    return a;
}
__device__ __forceinline__ void ldsm4(uint32_t& r0, uint32_t& r1, uint32_t& r2, uint32_t& r3,
                                      uint32_t addr) {
    asm volatile("ldmatrix.sync.aligned.m8n8.x4.shared.b16 {%0,%1,%2,%3}, [%4];"
                 : "=r"(r0), "=r"(r1), "=r"(r2), "=r"(r3) : "r"(addr));
}
template <int KIND>   // 0 = fp16, 1 = bf16
__device__ __forceinline__ void mma16816(float (&d)[4], const uint32_t (&a)[4],
                                         uint32_t b0, uint32_t b1) {
    if (KIND == 0)
        asm volatile("mma.sync.aligned.m16n8k16.row.col.f32.f16.f16.f32 "
                     "{%0,%1,%2,%3}, {%4,%5,%6,%7}, {%8,%9}, {%0,%1,%2,%3};"
                     : "+f"(d[0]), "+f"(d[1]), "+f"(d[2]), "+f"(d[3])
                     : "r"(a[0]), "r"(a[1]), "r"(a[2]), "r"(a[3]), "r"(b0), "r"(b1));
    else
        asm volatile("mma.sync.aligned.m16n8k16.row.col.f32.bf16.bf16.f32 "
                     "{%0,%1,%2,%3}, {%4,%5,%6,%7}, {%8,%9}, {%0,%1,%2,%3};"
                     : "+f"(d[0]), "+f"(d[1]), "+f"(d[2]), "+f"(d[3])
                     : "r"(a[0]), "r"(a[1]), "r"(a[2]), "r"(a[3]), "r"(b0), "r"(b1));
}
// exp on the FMA pipe (no MUFU)
__device__ __forceinline__ float fast_exp(float x) {
    float y = x * 1.4426950408889634f;
    int ni = __float2int_rn(y);
    ni = max(ni, -120);
    float f = y - (float)ni;
    float p = 1.3333558146e-3f;
    p = fmaf(p, f, 9.6181291076e-3f);
    p = fmaf(p, f, 5.5504108665e-2f);
    p = fmaf(p, f, 2.4022650696e-1f);
    p = fmaf(p, f, 6.9314718056e-1f);
    p = fmaf(p, f, 1.0f);
    return __int_as_float(__float_as_int(p) + (ni << 23));
}
__device__ __forceinline__ uint32_t pack_h2(float a, float b) {
    __half2 h = __floats2half2_rn(a, b);
    return *reinterpret_cast<uint32_t*>(&h);
}

// stage 128 rows x 32 16-bit elems (already 16-bit in gmem) into [128][ROWH]
__device__ __forceinline__ void stage16(char* s, const uint16_t* src, int rstride,
                                        int row0, int k0, int tid) {
#pragma unroll
    for (int it = 0; it < 2; it++) {
        int u = it * 256 + tid;
        int row = u & 127, ch = u >> 7;                  // warp rows contiguous, same chunk
        uint4 v = *(const uint4*)(src + (size_t)(row0 + row) * rstride + k0 + ch * 8);
        *(uint4*)(s + row * (ROWH * 2) + ch * 16) = v;
    }
}
// stage with fp32 -> fp16 conversion
__device__ __forceinline__ void stage_cvt(char* s, const float* src, int rstride,
                                          int row0, int k0, int tid) {
#pragma unroll
    for (int it = 0; it < 2; it++) {
        int u = it * 256 + tid;
        int row = u & 127, ch = u >> 7;
        const float* p = src + (size_t)(row0 + row) * rstride + k0 + ch * 8;
        float4 a = *(const float4*)(p);
        float4 b = *(const float4*)(p + 4);
        uint4 o = make_uint4(pack_h2(a.x, a.y), pack_h2(a.z, a.w),
                             pack_h2(b.x, b.y), pack_h2(b.z, b.w));
        *(uint4*)(s + row * (ROWH * 2) + ch * 16) = o;
    }
}

// one staged 32-deep K slab: 4 A-ldsm, 8 B-ldsm, 32 mma
template <int KIND>
__device__ __forceinline__ void slab(uint32_t aB, uint32_t bB, float (&acc)[2][8][4]) {
#pragma unroll
    for (int ks = 0; ks < 2; ks++) {
        uint32_t af[2][4];
#pragma unroll
        for (int mt = 0; mt < 2; mt++)
            ldsm4(af[mt][0], af[mt][1], af[mt][2], af[mt][3],
                  aB + mt * (16 * ROWH * 2) + ks * 32);
#pragma unroll
        for (int np = 0; np < 4; np++) {
            uint32_t q0, q1, q2, q3;
            ldsm4(q0, q1, q2, q3, bB + np * (16 * ROWH * 2) + ks * 32);
#pragma unroll
            for (int mt = 0; mt < 2; mt++) {
                mma16816<KIND>(acc[mt][2 * np],     af[mt], q0, q1);
                mma16816<KIND>(acc[mt][2 * np + 1], af[mt], q2, q3);
            }
        }
    }
}
// per-warp lane addressing into the padded tiles
__device__ __forceinline__ uint32_t a_base(const void* sA, int M0, int lane) {
    return smem_u32(sA) + (uint32_t)((M0 + (lane & 15)) * (ROWH * 2)) + (uint32_t)((lane >> 4) * 16);
}
__device__ __forceinline__ uint32_t b_base(const void* sB, int N0, int lane) {
    int row = N0 + (lane & 7) + ((lane >> 4) & 1) * 8;
    return smem_u32(sB) + (uint32_t)(row * (ROWH * 2)) + (uint32_t)(((lane >> 3) & 1) * 16);
}

// ---------------- tiny kernels ----------------------------------------------
__global__ void __launch_bounds__(256) k_zero() {
    int i = blockIdx.x * 256 + threadIdx.x;
    (&g_Z[0][0])[i] = 0.0f;
}
__global__ void __launch_bounds__(256) k_recip() {
    int i = blockIdx.x * 256 + threadIdx.x;
    float* z = &g_Z[0][0];
    z[i] = 1.0f / z[i];
}
__global__ void __launch_bounds__(256) k_sumY() {
    int i = blockIdx.x * 256 + threadIdx.x;              // 2048 blocks -> 2M float4 groups /4
    const int b = i / (NN * CH / 4);
    const int o = (i % (NN * CH / 4)) * 4;
    float4 s0 = *(const float4*)(&g_Yp[0][b][o]);
    float4 s1 = *(const float4*)(&g_Yp[1][b][o]);
    float4 s2 = *(const float4*)(&g_Yp[2][b][o]);
    float4 s3 = *(const float4*)(&g_Yp[3][b][o]);
    float x0 = s0.x + s1.x + s2.x + s3.x;
    float x1 = s0.y + s1.y + s2.y + s3.y;
    float x2 = s0.z + s1.z + s2.z + s3.z;
    float x3 = s0.w + s1.w + s2.w + s3.w;
    *(uint2*)(&g_Y[b][o]) = make_uint2(pack_h2(x0, x1), pack_h2(x2, x3));
}

// ---------------- transposes -------------------------------------------------
__global__ void __launch_bounds__(256) k_transX(const float* __restrict__ x) {
    __shared__ float t[32][33];
    const int b = blockIdx.z;
    const float* src = x + (size_t)b * CIN * NN;
    __half* dst = g_Xt[b];
    const int c0 = blockIdx.x * 32, r0 = blockIdx.y * 32;   // c over NN, r over CIN
    const int tx = threadIdx.x, ty = threadIdx.y;
#pragma unroll
    for (int j = 0; j < 32; j += 8) t[ty + j][tx] = src[(size_t)(r0 + ty + j) * NN + c0 + tx];
    __syncthreads();
#pragma unroll
    for (int j = 0; j < 32; j += 8)
        dst[(size_t)(c0 + ty + j) * CIN + r0 + tx] = __float2half(t[tx][ty + j]);
}
__global__ void __launch_bounds__(256) k_transG() {
    __shared__ float t[32][33];
    const int b = blockIdx.z;
    const __half* src = g_G[b];         // flat == x3 (NN,CH)
    const float* rZ  = g_Z[b];
    __nv_bfloat16* dst = g_Gt[b];
    const int c0 = blockIdx.x * 32;     // over CH
    const int r0 = blockIdx.y * 32;     // over NN
    const int tx = threadIdx.x, ty = threadIdx.y;
#pragma unroll
    for (int j = 0; j < 32; j += 8)
        t[ty + j][tx] = __half2float(src[(size_t)(r0 + ty + j) * CH + c0 + tx]) * rZ[r0 + ty + j];
    __syncthreads();
#pragma unroll
    for (int j = 0; j < 32; j += 8)
        dst[(size_t)(c0 + ty + j) * NN + r0 + tx] = __float2bfloat16(t[tx][ty + j]);
}

// ---------------- K1a: theta/gi convs -> (CH,NN) fp16 ------------------------
__global__ void __launch_bounds__(256) k_qkv_cn(
    const float* __restrict__ tw, const float* __restrict__ tb,
    const float* __restrict__ gw, const float* __restrict__ gb)
{
    __shared__ __align__(16) char sA[128 * ROWH * 2];
    __shared__ __align__(16) char sB[128 * ROWH * 2];
    const int tid = threadIdx.x, lane = tid & 31, wid = tid >> 5;
    const int b = blockIdx.z, sec = blockIdx.y, j0 = blockIdx.x * 128;
    const float* W  = sec == 0 ? tw : gw;
    const float* Bv = sec == 0 ? tb : gb;
    __half*    Dst  = sec == 0 ? g_T[b] : g_G[b];
    const uint16_t* Xt = (const uint16_t*)g_Xt[b];

    const int g = lane >> 2, tg = lane & 3;
    const int M0 = (wid & 3) * 32, N0 = (wid >> 2) * 64;
    const uint32_t aB = a_base(sA, M0, lane), bB = b_base(sB, N0, lane);

    float acc[2][8][4] = {};
    for (int k0 = 0; k0 < CIN; k0 += 32) {
        stage_cvt(sA, W, CIN, 0, k0, tid);
        stage16(sB, Xt, CIN, j0, k0, tid);
        __syncthreads();
        slab<0>(aB, bB, acc);
        __syncthreads();
    }
#pragma unroll
    for (int mt = 0; mt < 2; mt++) {
        int r = M0 + mt * 16 + g;
        float b0 = Bv[r], b1 = Bv[r + 8];
#pragma unroll
        for (int nt = 0; nt < 8; nt++) {
            int c = j0 + N0 + nt * 8 + 2 * tg;
            *(__half2*)(Dst + (size_t)r * NN + c)       = __floats2half2_rn(acc[mt][nt][0] + b0, acc[mt][nt][1] + b0);
            *(__half2*)(Dst + (size_t)(r + 8) * NN + c) = __floats2half2_rn(acc[mt][nt][2] + b1, acc[mt][nt][3] + b1);
        }
    }
}

// ---------------- K1b: fi conv computed directly as Ft (NN,CH) fp16 ----------
__global__ void __launch_bounds__(256) k_fi_nc(
    const float* __restrict__ fw, const float* __restrict__ fb)
{
    __shared__ __align__(16) char sA[128 * ROWH * 2];
    __shared__ __align__(16) char sB[128 * ROWH * 2];
    const int tid = threadIdx.x, lane = tid & 31, wid = tid >> 5;
    const int b = blockIdx.z, i0 = blockIdx.x * 128;
    const uint16_t* Xt = (const uint16_t*)g_Xt[b];
    __half* Dst = g_Ft[b];

    const int g = lane >> 2, tg = lane & 3;
    const int M0 = (wid & 3) * 32, N0 = (wid >> 2) * 64;
    const uint32_t aB = a_base(sA, M0, lane), bB = b_base(sB, N0, lane);

    float acc[2][8][4] = {};
    for (int k0 = 0; k0 < CIN; k0 += 32) {
        stage16(sA, Xt, CIN, i0, k0, tid);
        stage_cvt(sB, fw, CIN, 0, k0, tid);
        __syncthreads();
        slab<0>(aB, bB, acc);
        __syncthreads();
    }
#pragma unroll
    for (int mt = 0; mt < 2; mt++) {
        int r = i0 + M0 + mt * 16 + g;
#pragma unroll
        for (int nt = 0; nt < 8; nt++) {
            int c = N0 + nt * 8 + 2 * tg;
            float b0 = fb[c], b1 = fb[c + 1];
            *(__half2*)(Dst + (size_t)r * CH + c)       = __floats2half2_rn(acc[mt][nt][0] + b0, acc[mt][nt][1] + b1);
            *(__half2*)(Dst + (size_t)(r + 8) * CH + c) = __floats2half2_rn(acc[mt][nt][2] + b0, acc[mt][nt][3] + b1);
        }
    }
}

// ---------------- K2: E = exp(x1 @ x2) fp16 mma, fused col-sums --------------
__global__ void __launch_bounds__(256) k_scores() {
    __shared__ __align__(16) char sA[128 * ROWH * 2];
    __shared__ __align__(16) char sB[128 * ROWH * 2];
    const int tid = threadIdx.x, lane = tid & 31, wid = tid >> 5;
    const int b = blockIdx.z, i0 = blockIdx.y * 128, j0 = blockIdx.x * 128;
    const uint16_t* A  = (const uint16_t*)g_T[b];    // (N,CH) flat view
    const uint16_t* Bm = (const uint16_t*)g_Ft[b];   // (N,CH)
    __nv_bfloat16*  E  = g_E[b];

    const int g = lane >> 2, tg = lane & 3;
    const int M0 = (wid & 3) * 32, N0 = (wid >> 2) * 64;
    const uint32_t aB = a_base(sA, M0, lane), bB = b_base(sB, N0, lane);

    float acc[2][8][4] = {};
    for (int k0 = 0; k0 < CH; k0 += 32) {
        stage16(sA, A, CH, i0, k0, tid);
        stage16(sB, Bm, CH, j0, k0, tid);
        __syncthreads();
        slab<0>(aB, bB, acc);
        __syncthreads();
    }
#pragma unroll
    for (int nt = 0; nt < 8; nt++) {
        float cs0 = 0.f, cs1 = 0.f;
#pragma unroll
        for (int mt = 0; mt < 2; mt++) {
            float e0 = fast_exp(acc[mt][nt][0]);
            float e1 = fast_exp(acc[mt][nt][1]);
            float e2 = fast_exp(acc[mt][nt][2]);
            float e3 = fast_exp(acc[mt][nt][3]);
            int r = i0 + M0 + mt * 16 + g;
            int c = j0 + N0 + nt * 8 + 2 * tg;
            *(__nv_bfloat162*)(E + (size_t)r * NN + c)       = __floats2bfloat162_rn(e0, e1);
            *(__nv_bfloat162*)(E + (size_t)(r + 8) * NN + c) = __floats2bfloat162_rn(e2, e3);
            cs0 += e0 + e2;
            cs1 += e1 + e3;
        }
        cs0 += __shfl_xor_sync(0xFFFFFFFFu, cs0, 4);
        cs0 += __shfl_xor_sync(0xFFFFFFFFu, cs0, 8);
        cs0 += __shfl_xor_sync(0xFFFFFFFFu, cs0, 16);
        cs1 += __shfl_xor_sync(0xFFFFFFFFu, cs1, 4);
        cs1 += __shfl_xor_sync(0xFFFFFFFFu, cs1, 8);
        cs1 += __shfl_xor_sync(0xFFFFFFFFu, cs1, 16);
        if (lane < 4) {
            int c = j0 + N0 + nt * 8 + 2 * tg;
            atomicAdd(&g_Z[b][c],     cs0);
            atomicAdd(&g_Z[b][c + 1], cs1);
        }
    }
}

// ---------------- K4: Yp[ks] = E-slice @ Gt^T, bf16 mma ----------------------
__global__ void __launch_bounds__(256) k_attnv() {
    __shared__ __align__(16) char sA[128 * ROWH * 2];
    __shared__ __align__(16) char sB[128 * ROWH * 2];
    const int tid = threadIdx.x, lane = tid & 31, wid = tid >> 5;
    const int ks = blockIdx.x, i0 = blockIdx.y * 128, b = blockIdx.z;
    const int kbase = ks * (NN / KSPLIT);
    const uint16_t* E  = (const uint16_t*)g_E[b];
    const uint16_t* Gt = (const uint16_t*)g_Gt[b];   // (CH, NN)
    float* Yp = g_Yp[ks][b];

    const int g = lane >> 2, tg = lane & 3;
    const int M0 = (wid & 3) * 32, N0 = (wid >> 2) * 64;
    const uint32_t aB = a_base(sA, M0, lane), bB = b_base(sB, N0, lane);

    float acc[2][8][4] = {};
    for (int cc = 0; cc < (NN / KSPLIT) / 32; cc++) {
        const int k0 = kbase + cc * 32;
        stage16(sA, E, NN, i0, k0, tid);
        stage16(sB, Gt, NN, 0, k0, tid);
        __syncthreads();
        slab<1>(aB, bB, acc);
        __syncthreads();
    }
#pragma unroll
    for (int mt = 0; mt < 2; mt++) {
        int r = i0 + M0 + mt * 16 + g;
#pragma unroll
        for (int nt = 0; nt < 8; nt++) {
            int c = N0 + nt * 8 + 2 * tg;
            *(float2*)(Yp + (size_t)r * CH + c)       = make_float2(acc[mt][nt][0], acc[mt][nt][1]);
            *(float2*)(Yp + (size_t)(r + 8) * CH + c) = make_float2(acc[mt][nt][2], acc[mt][nt][3]);
        }
    }
}

// ---------------- K5: out = x + out_w @ Y^T + out_b, fp16 mma ----------------
__global__ void __launch_bounds__(256) k_out(
    const float* __restrict__ x,
    const float* __restrict__ ow, const float* __restrict__ ob,
    float* __restrict__ out)
{
    __shared__ __align__(16) char sA[128 * ROWH * 2];
    __shared__ __align__(16) char sB[128 * ROWH * 2];
    const int tid = threadIdx.x, lane = tid & 31, wid = tid >> 5;
    const int b = blockIdx.z, m0 = blockIdx.y * 128, n0 = blockIdx.x * 128;
    const uint16_t* Y = (const uint16_t*)g_Y[b];

    const int g = lane >> 2, tg = lane & 3;
    const int M0 = (wid & 3) * 32, N0 = (wid >> 2) * 64;
    const uint32_t aB = a_base(sA, M0, lane), bB = b_base(sB, N0, lane);

    float acc[2][8][4] = {};
    for (int k0 = 0; k0 < CH; k0 += 32) {
        stage_cvt(sA, ow, CH, m0, k0, tid);
        stage16(sB, Y, CH, n0, k0, tid);
        __syncthreads();
        slab<0>(aB, bB, acc);
        __syncthreads();
    }
#pragma unroll
    for (int mt = 0; mt < 2; mt++) {
        int r = m0 + M0 + mt * 16 + g;
        float b0 = ob[r], b1 = ob[r + 8];
#pragma unroll
        for (int nt = 0; nt < 8; nt++) {
            int c = n0 + N0 + nt * 8 + 2 * tg;
            size_t o0 = ((size_t)b * CIN + r) * NN + c;
            size_t o1 = ((size_t)b * CIN + r + 8) * NN + c;
            float2 x0 = *(const float2*)(x + o0);
            float2 x1 = *(const float2*)(x + o1);
            *(float2*)(out + o0) = make_float2(acc[mt][nt][0] + b0 + x0.x, acc[mt][nt][1] + b0 + x0.y);
            *(float2*)(out + o1) = make_float2(acc[mt][nt][2] + b1 + x1.x, acc[mt][nt][3] + b1 + x1.y);
        }
    }
}

// -----------------------------------------------------------------------------
extern "C" void kernel_launch(void* const* d_in, const int* in_sizes, int n_in,
                              void* d_out, int out_size) {
    const float* x  = (const float*)d_in[0];
    const float* tw = (const float*)d_in[1];
    const float* tb = (const float*)d_in[2];
    const float* fw = (const float*)d_in[3];
    const float* fb = (const float*)d_in[4];
    const float* gw = (const float*)d_in[5];
    const float* gb = (const float*)d_in[6];
    const float* ow = (const float*)d_in[7];
    const float* ob = (const float*)d_in[8];
    float* out = (float*)d_out;

    k_zero<<<64, 256>>>();
    k_transX<<<dim3(128, 8, BATCH), dim3(32, 8)>>>(x);
    k_qkv_cn<<<dim3(32, 2, BATCH), 256>>>(tw, tb, gw, gb);
    k_fi_nc<<<dim3(32, 1, BATCH), 256>>>(fw, fb);
    k_scores<<<dim3(32, 32, BATCH), 256>>>();
    k_recip<<<64, 256>>>();
    k_transG<<<dim3(4, 128, BATCH), dim3(32, 8)>>>();
    k_attnv<<<dim3(KSPLIT, 32, BATCH), 256>>>();
    k_sumY<<<2048, 256>>>();
    k_out<<<dim3(32, 2, BATCH), 256>>>(x, ow, ob, out);
}

// round 5
// speedup vs baseline: 5.5757x; 1.3613x over previous
#include <cuda_runtime.h>
#include <cuda_fp16.h>
#include <cuda_bf16.h>
#include <cstdint>

#define BATCH 4
#define CIN   256
#define CH    128
#define NN    4096
#define ROWH  40                 /* padded smem row length in 16-bit elems (80 B) */
#define TBY   (128 * ROWH * 2)   /* one tile buffer: 10240 bytes */
#define KSPLIT 4

// ---------------- scratch (device globals; no allocs allowed) ----------------
__device__ __align__(16) __half        g_Wh[4][CIN * CH];            // fp16 weights: teta, gi, fi, out
__device__ __align__(16) __half        g_Xt[BATCH][NN * CIN];        // x^T: (NN, CIN) fp16
__device__ __align__(16) __half        g_T [BATCH][CH * NN];         // theta out (CH,NN) flat == x1 (N,CH)
__device__ __align__(16) __half        g_G [BATCH][CH * NN];         // gi out flat == x3 (N,CH)
__device__ __align__(16) __half        g_Ft[BATCH][NN * CH];         // fi out as (NN, CH)
__device__ __align__(16) __nv_bfloat16 g_Gt[BATCH][CH * NN];         // x3^T * invZ: (CH, NN) bf16
__device__ __align__(16) __nv_bfloat16 g_E [BATCH][(size_t)NN * NN]; // exp(S) bf16
__device__ __align__(16) float         g_Z [BATCH][NN];              // column sums -> reciprocals
__device__ __align__(16) float         g_Yp[KSPLIT][BATCH][NN * CH]; // split-K partials of Y
__device__ __align__(16) __half        g_Y [BATCH][NN * CH];         // summed Y (N,CH) fp16

// ====================== helpers (baseline PTX only) ==========================
__device__ __forceinline__ uint32_t smem_u32(const void* p) {
    uint32_t a;
    asm("{ .reg .u64 t; cvta.to.shared.u64 t, %1; cvt.u32.u64 %0, t; }" : "=r"(a) : "l"(p));
    return a;
}
__device__ __forceinline__ void cpa16(uint32_t s, const void* g) {
    asm volatile("cp.async.cg.shared.global [%0], [%1], 16;" :: "r"(s), "l"(g));
}
#define CPA_COMMIT() asm volatile("cp.async.commit_group;" ::: "memory")
#define CPA_WAIT0()  asm volatile("cp.async.wait_group 0;" ::: "memory")

__device__ __forceinline__ void ldsm4(uint32_t& r0, uint32_t& r1, uint32_t& r2, uint32_t& r3,
                                      uint32_t addr) {
    asm volatile("ldmatrix.sync.aligned.m8n8.x4.shared.b16 {%0,%1,%2,%3}, [%4];"
                 : "=r"(r0), "=r"(r1), "=r"(r2), "=r"(r3) : "r"(addr));
}
template <int KIND>   // 0 = fp16, 1 = bf16
__device__ __forceinline__ void mma16816(float (&d)[4], const uint32_t (&a)[4],
                                         uint32_t b0, uint32_t b1) {
    if (KIND == 0)
        asm volatile("mma.sync.aligned.m16n8k16.row.col.f32.f16.f16.f32 "
                     "{%0,%1,%2,%3}, {%4,%5,%6,%7}, {%8,%9}, {%0,%1,%2,%3};"
                     : "+f"(d[0]), "+f"(d[1]), "+f"(d[2]), "+f"(d[3])
                     : "r"(a[0]), "r"(a[1]), "r"(a[2]), "r"(a[3]), "r"(b0), "r"(b1));
    else
        asm volatile("mma.sync.aligned.m16n8k16.row.col.f32.bf16.bf16.f32 "
                     "{%0,%1,%2,%3}, {%4,%5,%6,%7}, {%8,%9}, {%0,%1,%2,%3};"
                     : "+f"(d[0]), "+f"(d[1]), "+f"(d[2]), "+f"(d[3])
                     : "r"(a[0]), "r"(a[1]), "r"(a[2]), "r"(a[3]), "r"(b0), "r"(b1));
}
// exp on the FMA pipe (no MUFU)
__device__ __forceinline__ float fast_exp(float x) {
    float y = x * 1.4426950408889634f;
    int ni = __float2int_rn(y);
    ni = max(ni, -120);
    float f = y - (float)ni;
    float p = 1.3333558146e-3f;
    p = fmaf(p, f, 9.6181291076e-3f);
    p = fmaf(p, f, 5.5504108665e-2f);
    p = fmaf(p, f, 2.4022650696e-1f);
    p = fmaf(p, f, 6.9314718056e-1f);
    p = fmaf(p, f, 1.0f);
    return __int_as_float(__float_as_int(p) + (ni << 23));
}
__device__ __forceinline__ uint32_t pack_h2(float a, float b) {
    __half2 h = __floats2half2_rn(a, b);
    return *reinterpret_cast<uint32_t*>(&h);
}

// async-stage a 128x32 16-bit tile into the buffer at smem byte address sbase
__device__ __forceinline__ void stage_a(uint32_t sbase, const uint16_t* src, int rstride,
                                        int row0, int k0, int tid) {
#pragma unroll
    for (int it = 0; it < 2; it++) {
        int u = it * 256 + tid;
        int row = u & 127, ch = u >> 7;
        cpa16(sbase + (uint32_t)(row * (ROWH * 2) + ch * 16),
              src + (size_t)(row0 + row) * rstride + k0 + ch * 8);
    }
}

// one staged 32-deep K slab: 4 A-ldsm, 8 B-ldsm, 32 mma
template <int KIND>
__device__ __forceinline__ void slab(uint32_t aB, uint32_t bB, float (&acc)[2][8][4]) {
#pragma unroll
    for (int ks = 0; ks < 2; ks++) {
        uint32_t af[2][4];
#pragma unroll
        for (int mt = 0; mt < 2; mt++)
            ldsm4(af[mt][0], af[mt][1], af[mt][2], af[mt][3],
                  aB + mt * (16 * ROWH * 2) + ks * 32);
#pragma unroll
        for (int np = 0; np < 4; np++) {
            uint32_t q0, q1, q2, q3;
            ldsm4(q0, q1, q2, q3, bB + np * (16 * ROWH * 2) + ks * 32);
#pragma unroll
            for (int mt = 0; mt < 2; mt++) {
                mma16816<KIND>(acc[mt][2 * np],     af[mt], q0, q1);
                mma16816<KIND>(acc[mt][2 * np + 1], af[mt], q2, q3);
            }
        }
    }
}
__device__ __forceinline__ uint32_t a_base(const void* sA, int M0, int lane) {
    return smem_u32(sA) + (uint32_t)((M0 + (lane & 15)) * (ROWH * 2)) + (uint32_t)((lane >> 4) * 16);
}
__device__ __forceinline__ uint32_t b_base(const void* sB, int N0, int lane) {
    int row = N0 + (lane & 7) + ((lane >> 4) & 1) * 8;
    return smem_u32(sB) + (uint32_t)(row * (ROWH * 2)) + (uint32_t)(((lane >> 3) & 1) * 16);
}

// ---------------- tiny kernels ----------------------------------------------
__global__ void __launch_bounds__(256) k_cvtW(
    const float* __restrict__ tw, const float* __restrict__ gw,
    const float* __restrict__ fw, const float* __restrict__ ow)
{
    int i = blockIdx.x * 256 + threadIdx.x;          // 512 blocks * 256 = 131072
    int which = i >> 15, o = i & 32767;
    const float* src = which == 0 ? tw : (which == 1 ? gw : (which == 2 ? fw : ow));
    g_Wh[which][o] = __float2half(src[o]);
}
__global__ void __launch_bounds__(256) k_zero() {
    int i = blockIdx.x * 256 + threadIdx.x;
    (&g_Z[0][0])[i] = 0.0f;
}
__global__ void __launch_bounds__(256) k_recip() {
    int i = blockIdx.x * 256 + threadIdx.x;
    float* z = &g_Z[0][0];
    z[i] = 1.0f / z[i];
}
__global__ void __launch_bounds__(256) k_sumY() {
    int i = blockIdx.x * 256 + threadIdx.x;
    const int b = i / (NN * CH / 4);
    const int o = (i % (NN * CH / 4)) * 4;
    float4 s0 = *(const float4*)(&g_Yp[0][b][o]);
    float4 s1 = *(const float4*)(&g_Yp[1][b][o]);
    float4 s2 = *(const float4*)(&g_Yp[2][b][o]);
    float4 s3 = *(const float4*)(&g_Yp[3][b][o]);
    *(uint2*)(&g_Y[b][o]) = make_uint2(pack_h2(s0.x + s1.x + s2.x + s3.x, s0.y + s1.y + s2.y + s3.y),
                                       pack_h2(s0.z + s1.z + s2.z + s3.z, s0.w + s1.w + s2.w + s3.w));
}

// ---------------- transposes -------------------------------------------------
__global__ void __launch_bounds__(256) k_transX(const float* __restrict__ x) {
    __shared__ float t[32][33];
    const int b = blockIdx.z;
    const float* src = x + (size_t)b * CIN * NN;
    __half* dst = g_Xt[b];
    const int c0 = blockIdx.x * 32, r0 = blockIdx.y * 32;
    const int tx = threadIdx.x, ty = threadIdx.y;
#pragma unroll
    for (int j = 0; j < 32; j += 8) t[ty + j][tx] = src[(size_t)(r0 + ty + j) * NN + c0 + tx];
    __syncthreads();
#pragma unroll
    for (int j = 0; j < 32; j += 8)
        dst[(size_t)(c0 + ty + j) * CIN + r0 + tx] = __float2half(t[tx][ty + j]);
}
__global__ void __launch_bounds__(256) k_transG() {
    __shared__ float t[32][33];
    const int b = blockIdx.z;
    const __half* src = g_G[b];
    const float* rZ  = g_Z[b];
    __nv_bfloat16* dst = g_Gt[b];
    const int c0 = blockIdx.x * 32;     // over CH
    const int r0 = blockIdx.y * 32;     // over NN
    const int tx = threadIdx.x, ty = threadIdx.y;
#pragma unroll
    for (int j = 0; j < 32; j += 8)
        t[ty + j][tx] = __half2float(src[(size_t)(r0 + ty + j) * CH + c0 + tx]) * rZ[r0 + ty + j];
    __syncthreads();
#pragma unroll
    for (int j = 0; j < 32; j += 8)
        dst[(size_t)(c0 + ty + j) * NN + r0 + tx] = __float2bfloat16(t[tx][ty + j]);
}

// ---------------- K1: theta/gi/fi convs, pipelined ---------------------------
__global__ void __launch_bounds__(256) k_qkv(
    const float* __restrict__ tb, const float* __restrict__ gb,
    const float* __restrict__ fb)
{
    __shared__ __align__(16) char sA[2 * TBY];
    __shared__ __align__(16) char sB[2 * TBY];
    const int tid = threadIdx.x, lane = tid & 31, wid = tid >> 5;
    const int b = blockIdx.z, sec = blockIdx.y, j0 = blockIdx.x * 128;
    const uint16_t* Xt = (const uint16_t*)g_Xt[b];
    const uint16_t* Wh = (const uint16_t*)g_Wh[sec];  // 0=teta, 1=gi, 2=fi

    const int g = lane >> 2, tg = lane & 3;
    const int M0 = (wid & 3) * 32, N0 = (wid >> 2) * 64;
    const uint32_t aB = a_base(sA, M0, lane), bB = b_base(sB, N0, lane);
    const uint32_t sbA = smem_u32(sA), sbB = smem_u32(sB);

    // sec 0/1: A = W (CH rows), B = Xt rows j0.. ; sec 2 (fi): A = Xt rows j0.., B = W
    const uint16_t* Asrc = sec < 2 ? Wh : Xt;
    const uint16_t* Bsrc = sec < 2 ? Xt : Wh;
    const int arow0 = sec < 2 ? 0 : j0;
    const int brow0 = sec < 2 ? j0 : 0;

    float acc[2][8][4] = {};
    stage_a(sbA, Asrc, CIN, arow0, 0, tid);
    stage_a(sbB, Bsrc, CIN, brow0, 0, tid);
    CPA_COMMIT();
#pragma unroll
    for (int cc = 0; cc < CIN / 32; cc++) {
        const int cur = cc & 1;
        CPA_WAIT0();
        __syncthreads();
        if (cc + 1 < CIN / 32) {
            stage_a(sbA + (cur ^ 1) * TBY, Asrc, CIN, arow0, (cc + 1) * 32, tid);
            stage_a(sbB + (cur ^ 1) * TBY, Bsrc, CIN, brow0, (cc + 1) * 32, tid);
            CPA_COMMIT();
        }
        slab<0>(aB + cur * TBY, bB + cur * TBY, acc);
    }
    if (sec < 2) {                                   // output (CH, NN)
        __half* Dst = sec == 0 ? g_T[b] : g_G[b];
        const float* Bv = sec == 0 ? tb : gb;
#pragma unroll
        for (int mt = 0; mt < 2; mt++) {
            int r = M0 + mt * 16 + g;
            float b0 = Bv[r], b1 = Bv[r + 8];
#pragma unroll
            for (int nt = 0; nt < 8; nt++) {
                int c = j0 + N0 + nt * 8 + 2 * tg;
                *(__half2*)(Dst + (size_t)r * NN + c)       = __floats2half2_rn(acc[mt][nt][0] + b0, acc[mt][nt][1] + b0);
                *(__half2*)(Dst + (size_t)(r + 8) * NN + c) = __floats2half2_rn(acc[mt][nt][2] + b1, acc[mt][nt][3] + b1);
            }
        }
    } else {                                         // fi: output (NN, CH)
        __half* Dst = g_Ft[b];
#pragma unroll
        for (int mt = 0; mt < 2; mt++) {
            int r = j0 + M0 + mt * 16 + g;
#pragma unroll
            for (int nt = 0; nt < 8; nt++) {
                int c = N0 + nt * 8 + 2 * tg;
                float b0 = fb[c], b1 = fb[c + 1];
                *(__half2*)(Dst + (size_t)r * CH + c)       = __floats2half2_rn(acc[mt][nt][0] + b0, acc[mt][nt][1] + b1);
                *(__half2*)(Dst + (size_t)(r + 8) * CH + c) = __floats2half2_rn(acc[mt][nt][2] + b0, acc[mt][nt][3] + b1);
            }
        }
    }
}

// ---------------- K2: E = exp(x1 @ x2), pipelined fp16, fused col-sums -------
__global__ void __launch_bounds__(256) k_scores() {
    __shared__ __align__(16) char sA[2 * TBY];
    __shared__ __align__(16) char sB[2 * TBY];
    const int tid = threadIdx.x, lane = tid & 31, wid = tid >> 5;
    const int b = blockIdx.z, i0 = blockIdx.y * 128, j0 = blockIdx.x * 128;
    const uint16_t* A  = (const uint16_t*)g_T[b];    // (N,CH) flat
    const uint16_t* Bm = (const uint16_t*)g_Ft[b];   // (N,CH)
    __nv_bfloat16*  E  = g_E[b];

    const int g = lane >> 2, tg = lane & 3;
    const int M0 = (wid & 3) * 32, N0 = (wid >> 2) * 64;
    const uint32_t aB = a_base(sA, M0, lane), bB = b_base(sB, N0, lane);
    const uint32_t sbA = smem_u32(sA), sbB = smem_u32(sB);

    float acc[2][8][4] = {};
    stage_a(sbA, A, CH, i0, 0, tid);
    stage_a(sbB, Bm, CH, j0, 0, tid);
    CPA_COMMIT();
#pragma unroll
    for (int cc = 0; cc < CH / 32; cc++) {
        const int cur = cc & 1;
        CPA_WAIT0();
        __syncthreads();
        if (cc + 1 < CH / 32) {
            stage_a(sbA + (cur ^ 1) * TBY, A, CH, i0, (cc + 1) * 32, tid);
            stage_a(sbB + (cur ^ 1) * TBY, Bm, CH, j0, (cc + 1) * 32, tid);
            CPA_COMMIT();
        }
        slab<0>(aB + cur * TBY, bB + cur * TBY, acc);
    }
#pragma unroll
    for (int nt = 0; nt < 8; nt++) {
        float cs0 = 0.f, cs1 = 0.f;
#pragma unroll
        for (int mt = 0; mt < 2; mt++) {
            float e0 = fast_exp(acc[mt][nt][0]);
            float e1 = fast_exp(acc[mt][nt][1]);
            float e2 = fast_exp(acc[mt][nt][2]);
            float e3 = fast_exp(acc[mt][nt][3]);
            int r = i0 + M0 + mt * 16 + g;
            int c = j0 + N0 + nt * 8 + 2 * tg;
            *(__nv_bfloat162*)(E + (size_t)r * NN + c)       = __floats2bfloat162_rn(e0, e1);
            *(__nv_bfloat162*)(E + (size_t)(r + 8) * NN + c) = __floats2bfloat162_rn(e2, e3);
            cs0 += e0 + e2;
            cs1 += e1 + e3;
        }
        cs0 += __shfl_xor_sync(0xFFFFFFFFu, cs0, 4);
        cs0 += __shfl_xor_sync(0xFFFFFFFFu, cs0, 8);
        cs0 += __shfl_xor_sync(0xFFFFFFFFu, cs0, 16);
        cs1 += __shfl_xor_sync(0xFFFFFFFFu, cs1, 4);
        cs1 += __shfl_xor_sync(0xFFFFFFFFu, cs1, 8);
        cs1 += __shfl_xor_sync(0xFFFFFFFFu, cs1, 16);
        if (lane < 4) {
            int c = j0 + N0 + nt * 8 + 2 * tg;
            atomicAdd(&g_Z[b][c],     cs0);
            atomicAdd(&g_Z[b][c + 1], cs1);
        }
    }
}

// ---------------- K4: Yp[ks] = E-slice @ Gt^T, pipelined bf16 ----------------
__global__ void __launch_bounds__(256) k_attnv() {
    __shared__ __align__(16) char sA[2 * TBY];
    __shared__ __align__(16) char sB[2 * TBY];
    const int tid = threadIdx.x, lane = tid & 31, wid = tid >> 5;
    const int ks = blockIdx.x, i0 = blockIdx.y * 128, b = blockIdx.z;
    const int kbase = ks * (NN / KSPLIT);
    const uint16_t* E  = (const uint16_t*)g_E[b];
    const uint16_t* Gt = (const uint16_t*)g_Gt[b];
    float* Yp = g_Yp[ks][b];

    const int g = lane >> 2, tg = lane & 3;
    const int M0 = (wid & 3) * 32, N0 = (wid >> 2) * 64;
    const uint32_t aB = a_base(sA, M0, lane), bB = b_base(sB, N0, lane);
    const uint32_t sbA = smem_u32(sA), sbB = smem_u32(sB);

    float acc[2][8][4] = {};
    stage_a(sbA, E, NN, i0, kbase, tid);
    stage_a(sbB, Gt, NN, 0, kbase, tid);
    CPA_COMMIT();
    const int C = (NN / KSPLIT) / 32;
    for (int cc = 0; cc < C; cc++) {
        const int cur = cc & 1;
        CPA_WAIT0();
        __syncthreads();
        if (cc + 1 < C) {
            stage_a(sbA + (cur ^ 1) * TBY, E, NN, i0, kbase + (cc + 1) * 32, tid);
            stage_a(sbB + (cur ^ 1) * TBY, Gt, NN, 0, kbase + (cc + 1) * 32, tid);
            CPA_COMMIT();
        }
        slab<1>(aB + cur * TBY, bB + cur * TBY, acc);
    }
#pragma unroll
    for (int mt = 0; mt < 2; mt++) {
        int r = i0 + M0 + mt * 16 + g;
#pragma unroll
        for (int nt = 0; nt < 8; nt++) {
            int c = N0 + nt * 8 + 2 * tg;
            *(float2*)(Yp + (size_t)r * CH + c)       = make_float2(acc[mt][nt][0], acc[mt][nt][1]);
            *(float2*)(Yp + (size_t)(r + 8) * CH + c) = make_float2(acc[mt][nt][2], acc[mt][nt][3]);
        }
    }
}

// ---------------- K5: out = x + out_w @ Y^T + out_b, pipelined fp16 ----------
__global__ void __launch_bounds__(256) k_out(
    const float* __restrict__ x,
    const float* __restrict__ ob,
    float* __restrict__ out)
{
    __shared__ __align__(16) char sA[2 * TBY];
    __shared__ __align__(16) char sB[2 * TBY];
    const int tid = threadIdx.x, lane = tid & 31, wid = tid >> 5;
    const int b = blockIdx.z, m0 = blockIdx.y * 128, n0 = blockIdx.x * 128;
    const uint16_t* Y  = (const uint16_t*)g_Y[b];
    const uint16_t* Wo = (const uint16_t*)g_Wh[3];

    const int g = lane >> 2, tg = lane & 3;
    const int M0 = (wid & 3) * 32, N0 = (wid >> 2) * 64;
    const uint32_t aB = a_base(sA, M0, lane), bB = b_base(sB, N0, lane);
    const uint32_t sbA = smem_u32(sA), sbB = smem_u32(sB);

    float acc[2][8][4] = {};
    stage_a(sbA, Wo, CH, m0, 0, tid);
    stage_a(sbB, Y, CH, n0, 0, tid);
    CPA_COMMIT();
#pragma unroll
    for (int cc = 0; cc < CH / 32; cc++) {
        const int cur = cc & 1;
        CPA_WAIT0();
        __syncthreads();
        if (cc + 1 < CH / 32) {
            stage_a(sbA + (cur ^ 1) * TBY, Wo, CH, m0, (cc + 1) * 32, tid);
            stage_a(sbB + (cur ^ 1) * TBY, Y, CH, n0, (cc + 1) * 32, tid);
            CPA_COMMIT();
        }
        slab<0>(aB + cur * TBY, bB + cur * TBY, acc);
    }
#pragma unroll
    for (int mt = 0; mt < 2; mt++) {
        int r = m0 + M0 + mt * 16 + g;
        float b0 = ob[r], b1 = ob[r + 8];
#pragma unroll
        for (int nt = 0; nt < 8; nt++) {
            int c = n0 + N0 + nt * 8 + 2 * tg;
            size_t o0 = ((size_t)b * CIN + r) * NN + c;
            size_t o1 = ((size_t)b * CIN + r + 8) * NN + c;
            float2 x0 = *(const float2*)(x + o0);
            float2 x1 = *(const float2*)(x + o1);
            *(float2*)(out + o0) = make_float2(acc[mt][nt][0] + b0 + x0.x, acc[mt][nt][1] + b0 + x0.y);
            *(float2*)(out + o1) = make_float2(acc[mt][nt][2] + b1 + x1.x, acc[mt][nt][3] + b1 + x1.y);
        }
    }
}

// -----------------------------------------------------------------------------
extern "C" void kernel_launch(void* const* d_in, const int* in_sizes, int n_in,
                              void* d_out, int out_size) {
    const float* x  = (const float*)d_in[0];
    const float* tw = (const float*)d_in[1];
    const float* tb = (const float*)d_in[2];
    const float* fw = (const float*)d_in[3];
    const float* fb = (const float*)d_in[4];
    const float* gw = (const float*)d_in[5];
    const float* gb = (const float*)d_in[6];
    const float* ow = (const float*)d_in[7];
    const float* ob = (const float*)d_in[8];
    float* out = (float*)d_out;

    k_cvtW<<<512, 256>>>(tw, gw, fw, ow);
    k_zero<<<64, 256>>>();
    k_transX<<<dim3(128, 8, BATCH), dim3(32, 8)>>>(x);
    k_qkv<<<dim3(32, 3, BATCH), 256>>>(tb, gb, fb);
    k_scores<<<dim3(32, 32, BATCH), 256>>>();
    k_recip<<<64, 256>>>();
    k_transG<<<dim3(4, 128, BATCH), dim3(32, 8)>>>();
    k_attnv<<<dim3(KSPLIT, 32, BATCH), 256>>>();
    k_sumY<<<2048, 256>>>();
    k_out<<<dim3(32, 2, BATCH), 256>>>(x, ob, out);
}